// round 1
// baseline (speedup 1.0000x reference)
#include <cuda_runtime.h>

#define BLOCK 128
#define TJ 128
#define MM 16

__global__ __launch_bounds__(BLOCK) void rbf_tps_kernel(
    const float* __restrict__ x,
    const float* __restrict__ y,
    const float* __restrict__ shift,
    const float* __restrict__ scale,
    const float* __restrict__ coeffs,
    const int*   __restrict__ powers,
    float* __restrict__ out,
    int nx, int n, int r)
{
    // Staged tiles: y points (coords + |y|^2) and their 16 coeffs.
    __shared__ float4 ys[TJ];        // {yx, yy, yz, |y|^2}
    __shared__ float4 cs[TJ * 4];    // 16 coeffs per j as 4x float4

    const int ix = blockIdx.x * BLOCK + threadIdx.x;

    float xx = 0.f, xy = 0.f, xz = 0.f, x2 = 0.f;
    if (ix < nx) {
        xx = x[3 * ix + 0];
        xy = x[3 * ix + 1];
        xz = x[3 * ix + 2];
        x2 = fmaf(xx, xx, fmaf(xy, xy, xz * xz));
    }

    float acc[MM];
#pragma unroll
    for (int m = 0; m < MM; ++m) acc[m] = 0.f;

    const float4* __restrict__ c4 = reinterpret_cast<const float4*>(coeffs);

    for (int j0 = 0; j0 < n; j0 += TJ) {
        // ---- cooperative stage (BLOCK == TJ) ----
        {
            int j = j0 + threadIdx.x;
            float4 v = make_float4(0.f, 0.f, 0.f, 1.f);  // tail: s = x2+1 (finite), coeffs 0
            if (j < n) {
                v.x = y[3 * j + 0];
                v.y = y[3 * j + 1];
                v.z = y[3 * j + 2];
                v.w = fmaf(v.x, v.x, fmaf(v.y, v.y, v.z * v.z));
            }
            ys[threadIdx.x] = v;
#pragma unroll
            for (int k = 0; k < 4; ++k) {
                int i = threadIdx.x + k * BLOCK;      // 0..511
                int jl = i >> 2;                       // local j
                float4 c = make_float4(0.f, 0.f, 0.f, 0.f);
                if (j0 + jl < n) c = c4[(size_t)(j0 + jl) * 4 + (i & 3)];
                cs[i] = c;
            }
        }
        __syncthreads();

        // ---- mainloop: phi = 0.5*s*log(s), s = |x-y|^2 (no sqrt needed) ----
#pragma unroll 8
        for (int jj = 0; jj < TJ; ++jj) {
            float4 v = ys[jj];
            float t = fmaf(xx, v.x, fmaf(xy, v.y, xz * v.z));
            float s = fmaf(-2.f, t, x2 + v.w);
            s = fmaxf(s, 1e-14f);
            float phi = 0.5f * s * __logf(s);

            float4 c0 = cs[4 * jj + 0];
            float4 c1 = cs[4 * jj + 1];
            float4 c2 = cs[4 * jj + 2];
            float4 c3 = cs[4 * jj + 3];

            acc[0]  = fmaf(phi, c0.x, acc[0]);
            acc[1]  = fmaf(phi, c0.y, acc[1]);
            acc[2]  = fmaf(phi, c0.z, acc[2]);
            acc[3]  = fmaf(phi, c0.w, acc[3]);
            acc[4]  = fmaf(phi, c1.x, acc[4]);
            acc[5]  = fmaf(phi, c1.y, acc[5]);
            acc[6]  = fmaf(phi, c1.z, acc[6]);
            acc[7]  = fmaf(phi, c1.w, acc[7]);
            acc[8]  = fmaf(phi, c2.x, acc[8]);
            acc[9]  = fmaf(phi, c2.y, acc[9]);
            acc[10] = fmaf(phi, c2.z, acc[10]);
            acc[11] = fmaf(phi, c2.w, acc[11]);
            acc[12] = fmaf(phi, c3.x, acc[12]);
            acc[13] = fmaf(phi, c3.y, acc[13]);
            acc[14] = fmaf(phi, c3.z, acc[14]);
            acc[15] = fmaf(phi, c3.w, acc[15]);
        }
        __syncthreads();
    }

    if (ix < nx) {
        // ---- polynomial tail: monomials of xhat, generic in powers ----
        float xh[3];
#pragma unroll
        for (int d = 0; d < 3; ++d) xh[d] = (((d == 0) ? xx : (d == 1) ? xy : xz) - shift[d]) / scale[d];

        for (int k = 0; k < r; ++k) {
            float p = 1.f;
#pragma unroll
            for (int d = 0; d < 3; ++d) {
                int e = powers[k * 3 + d];
                for (int q = 0; q < e; ++q) p *= xh[d];
            }
            float4 c0 = c4[(size_t)(n + k) * 4 + 0];
            float4 c1 = c4[(size_t)(n + k) * 4 + 1];
            float4 c2 = c4[(size_t)(n + k) * 4 + 2];
            float4 c3 = c4[(size_t)(n + k) * 4 + 3];
            acc[0]  = fmaf(p, c0.x, acc[0]);
            acc[1]  = fmaf(p, c0.y, acc[1]);
            acc[2]  = fmaf(p, c0.z, acc[2]);
            acc[3]  = fmaf(p, c0.w, acc[3]);
            acc[4]  = fmaf(p, c1.x, acc[4]);
            acc[5]  = fmaf(p, c1.y, acc[5]);
            acc[6]  = fmaf(p, c1.z, acc[6]);
            acc[7]  = fmaf(p, c1.w, acc[7]);
            acc[8]  = fmaf(p, c2.x, acc[8]);
            acc[9]  = fmaf(p, c2.y, acc[9]);
            acc[10] = fmaf(p, c2.z, acc[10]);
            acc[11] = fmaf(p, c2.w, acc[11]);
            acc[12] = fmaf(p, c3.x, acc[12]);
            acc[13] = fmaf(p, c3.y, acc[13]);
            acc[14] = fmaf(p, c3.z, acc[14]);
            acc[15] = fmaf(p, c3.w, acc[15]);
        }

        float4* __restrict__ o4 = reinterpret_cast<float4*>(out);
        o4[(size_t)ix * 4 + 0] = make_float4(acc[0],  acc[1],  acc[2],  acc[3]);
        o4[(size_t)ix * 4 + 1] = make_float4(acc[4],  acc[5],  acc[6],  acc[7]);
        o4[(size_t)ix * 4 + 2] = make_float4(acc[8],  acc[9],  acc[10], acc[11]);
        o4[(size_t)ix * 4 + 3] = make_float4(acc[12], acc[13], acc[14], acc[15]);
    }
}

extern "C" void kernel_launch(void* const* d_in, const int* in_sizes, int n_in,
                              void* d_out, int out_size) {
    const float* x      = (const float*)d_in[0];
    const float* y      = (const float*)d_in[1];
    const float* shift  = (const float*)d_in[2];
    const float* scale  = (const float*)d_in[3];
    const float* coeffs = (const float*)d_in[4];
    const int*   powers = (const int*)d_in[5];

    int nx = in_sizes[0] / 3;
    int n  = in_sizes[1] / 3;
    int r  = in_sizes[5] / 3;

    int grid = (nx + BLOCK - 1) / BLOCK;
    rbf_tps_kernel<<<grid, BLOCK>>>(x, y, shift, scale, coeffs, powers,
                                    (float*)d_out, nx, n, r);
}

// round 3
// speedup vs baseline: 1.6236x; 1.6236x over previous
#include <cuda_runtime.h>
#include <cstdint>

#define BLOCK 128
#define MTILE 128
#define NK 64
#define MM 16
#define CSTRIDE 20   // floats per j-row in smem coeff tile (bank-spread pad; /4 = 5 float4)

// pack two fp32 -> bf16x2 register (lo in low half, hi in high half)
__device__ __forceinline__ uint32_t pack_bf16x2(float lo, float hi) {
    uint32_t d;
    asm("cvt.rn.bf16x2.f32 %0, %1, %2;" : "=r"(d) : "f"(hi), "f"(lo));
    return d;
}

// split (f0, f1) into bf16x2 hi and bf16x2 lo-residual
__device__ __forceinline__ void split2(float f0, float f1, uint32_t& hi, uint32_t& lo) {
    hi = pack_bf16x2(f0, f1);
    float h0 = __uint_as_float(hi << 16);
    float h1 = __uint_as_float(hi & 0xffff0000u);
    lo = pack_bf16x2(f0 - h0, f1 - h1);
}

__device__ __forceinline__ void mma_bf16(float* c, const uint32_t* a, uint32_t b0, uint32_t b1) {
    asm volatile(
        "mma.sync.aligned.m16n8k16.row.col.f32.bf16.bf16.f32 "
        "{%0,%1,%2,%3}, {%4,%5,%6,%7}, {%8,%9}, {%0,%1,%2,%3};"
        : "+f"(c[0]), "+f"(c[1]), "+f"(c[2]), "+f"(c[3])
        : "r"(a[0]), "r"(a[1]), "r"(a[2]), "r"(a[3]), "r"(b0), "r"(b1));
}

// phi = r^2 log r = 0.5 * s * ln(s),  s = |x-y|^2  (sqrt-free)
__device__ __forceinline__ float phi_f(float4 xr, float4 v) {
    float t = fmaf(xr.x, v.x, fmaf(xr.y, v.y, xr.z * v.z));
    float s = fmaf(-2.f, t, xr.w + v.w);
    s = fmaxf(s, 1e-14f);
    return (0.34657359027997264f * s) * __log2f(s);   // 0.5*ln2 * s * lg2(s)
}

__global__ __launch_bounds__(BLOCK) void rbf_tps_mma_kernel(
    const float* __restrict__ x,
    const float* __restrict__ y,
    const float* __restrict__ shift,
    const float* __restrict__ scale,
    const float* __restrict__ coeffs,
    const int*   __restrict__ powers,
    float* __restrict__ out,
    int nx, int n, int r)
{
    __shared__ float4 sx[MTILE];                 // x rows: coords + |x|^2
    __shared__ float4 sy[NK];                    // y chunk: coords + |y|^2
    __shared__ __align__(16) float sc[NK * CSTRIDE];  // coeff chunk [64][16] padded

    const int tid  = threadIdx.x;
    const int lane = tid & 31;
    const int w    = tid >> 5;
    const int t4   = lane & 3;
    const int g    = lane >> 2;

    float4* sc4 = reinterpret_cast<float4*>(sc);
    const float4* c4 = reinterpret_cast<const float4*>(coeffs);

    // ---- stage x tile ----
    {
        int row = blockIdx.x * MTILE + tid;
        float4 v = make_float4(0.f, 0.f, 0.f, 0.f);
        if (row < nx) {
            v.x = x[3 * row + 0];
            v.y = x[3 * row + 1];
            v.z = x[3 * row + 2];
            v.w = fmaf(v.x, v.x, fmaf(v.y, v.y, v.z * v.z));
        }
        sx[tid] = v;
    }
    __syncthreads();

    float4 xr[4];
#pragma unroll
    for (int i = 0; i < 4; ++i) xr[i] = sx[w * 32 + g + 8 * i];

    float acc[2][2][4];
#pragma unroll
    for (int a = 0; a < 2; ++a)
#pragma unroll
        for (int b = 0; b < 2; ++b)
#pragma unroll
            for (int c = 0; c < 4; ++c) acc[a][b][c] = 0.f;

    const int nchunks = (n + NK - 1) / NK;

    // ---- prefetch chunk 0 ----
    float4 pyv = make_float4(0.f, 0.f, 0.f, 1.f);
    float4 pcv[2];
    {
        if (tid < NK) {
            int j = tid;
            if (j < n) {
                float a = y[3 * j], b = y[3 * j + 1], c = y[3 * j + 2];
                pyv = make_float4(a, b, c, fmaf(a, a, fmaf(b, b, c * c)));
            }
        }
#pragma unroll
        for (int q = 0; q < 2; ++q) {
            int idx = tid * 2 + q;
            int jj = idx >> 2;
            pcv[q] = (jj < n) ? c4[(size_t)jj * 4 + (idx & 3)]
                              : make_float4(0.f, 0.f, 0.f, 0.f);
        }
    }

    for (int t = 0; t < nchunks; ++t) {
        __syncthreads();
        // commit prefetched chunk t
        if (tid < NK) sy[tid] = pyv;
#pragma unroll
        for (int q = 0; q < 2; ++q) {
            int idx = tid * 2 + q;
            sc4[(idx >> 2) * (CSTRIDE / 4) + (idx & 3)] = pcv[q];
        }
        __syncthreads();

        // prefetch chunk t+1
        if (t + 1 < nchunks) {
            int j0n = (t + 1) * NK;
            pyv = make_float4(0.f, 0.f, 0.f, 1.f);
            if (tid < NK) {
                int j = j0n + tid;
                if (j < n) {
                    float a = y[3 * j], b = y[3 * j + 1], c = y[3 * j + 2];
                    pyv = make_float4(a, b, c, fmaf(a, a, fmaf(b, b, c * c)));
                }
            }
#pragma unroll
            for (int q = 0; q < 2; ++q) {
                int idx = tid * 2 + q;
                int jj = j0n + (idx >> 2);
                pcv[q] = (jj < n) ? c4[(size_t)jj * 4 + (idx & 3)]
                                  : make_float4(0.f, 0.f, 0.f, 0.f);
            }
        }

        // ---- compute: 4 k-steps of 16 ----
#pragma unroll
        for (int ks = 0; ks < 4; ++ks) {
            const int jb = ks * 16;
            const int j0 = jb + 2 * t4;
            float4 v0 = sy[j0], v1 = sy[j0 + 1], v2 = sy[j0 + 8], v3 = sy[j0 + 9];

            // B fragments: col n = g (+8 for second n8 tile), k-rows = the same 4 j's
            uint32_t bhi[2][2], blo[2][2];
            const int r0 = j0 * CSTRIDE, r1 = (j0 + 1) * CSTRIDE,
                      r2 = (j0 + 8) * CSTRIDE, r3 = (j0 + 9) * CSTRIDE;
#pragma unroll
            for (int nt = 0; nt < 2; ++nt) {
                int c = g + 8 * nt;
                float q0 = sc[r0 + c], q1 = sc[r1 + c];
                float q2 = sc[r2 + c], q3 = sc[r3 + c];
                split2(q0, q1, bhi[nt][0], blo[nt][0]);
                split2(q2, q3, bhi[nt][1], blo[nt][1]);
            }

#pragma unroll
            for (int rt = 0; rt < 2; ++rt) {
                float4 xa = xr[2 * rt], xb = xr[2 * rt + 1];
                float p00 = phi_f(xa, v0), p01 = phi_f(xa, v1);
                float p02 = phi_f(xa, v2), p03 = phi_f(xa, v3);
                float p10 = phi_f(xb, v0), p11 = phi_f(xb, v1);
                float p12 = phi_f(xb, v2), p13 = phi_f(xb, v3);

                uint32_t ah[4], al[4];
                split2(p00, p01, ah[0], al[0]);
                split2(p10, p11, ah[1], al[1]);
                split2(p02, p03, ah[2], al[2]);
                split2(p12, p13, ah[3], al[3]);

#pragma unroll
                for (int nt = 0; nt < 2; ++nt) {
                    mma_bf16(acc[rt][nt], ah, bhi[nt][0], bhi[nt][1]);
                    mma_bf16(acc[rt][nt], al, bhi[nt][0], bhi[nt][1]);
                    mma_bf16(acc[rt][nt], ah, blo[nt][0], blo[nt][1]);
                }
            }
        }
    }

    // ---- epilogue: polynomial part + store ----
    const float sh0 = __ldg(&shift[0]), sh1 = __ldg(&shift[1]), sh2 = __ldg(&shift[2]);
    const float sl0 = __ldg(&scale[0]), sl1 = __ldg(&scale[1]), sl2 = __ldg(&scale[2]);

#pragma unroll
    for (int i = 0; i < 4; ++i) {
        int grow = blockIdx.x * MTILE + w * 32 + g + 8 * i;
        if (grow >= nx) continue;
        float4 xc = xr[i];
        float xh0 = (xc.x - sh0) / sl0;
        float xh1 = (xc.y - sh1) / sl1;
        float xh2 = (xc.z - sh2) / sl2;
        const int rt = i >> 1, up = i & 1;

#pragma unroll
        for (int nt = 0; nt < 2; ++nt) {
            const int col = 2 * t4 + 8 * nt;
            float o0 = acc[rt][nt][up * 2 + 0];
            float o1 = acc[rt][nt][up * 2 + 1];
            for (int k = 0; k < r; ++k) {
                float p = 1.f;
                int e0 = __ldg(&powers[k * 3 + 0]);
                int e1 = __ldg(&powers[k * 3 + 1]);
                int e2 = __ldg(&powers[k * 3 + 2]);
                for (int q = 0; q < e0; ++q) p *= xh0;
                for (int q = 0; q < e1; ++q) p *= xh1;
                for (int q = 0; q < e2; ++q) p *= xh2;
                float cc0 = __ldg(&coeffs[(size_t)(n + k) * MM + col]);
                float cc1 = __ldg(&coeffs[(size_t)(n + k) * MM + col + 1]);
                o0 = fmaf(p, cc0, o0);
                o1 = fmaf(p, cc1, o1);
            }
            *reinterpret_cast<float2*>(&out[(size_t)grow * MM + col]) = make_float2(o0, o1);
        }
    }
}

extern "C" void kernel_launch(void* const* d_in, const int* in_sizes, int n_in,
                              void* d_out, int out_size) {
    const float* x      = (const float*)d_in[0];
    const float* y      = (const float*)d_in[1];
    const float* shift  = (const float*)d_in[2];
    const float* scale  = (const float*)d_in[3];
    const float* coeffs = (const float*)d_in[4];
    const int*   powers = (const int*)d_in[5];

    int nx = in_sizes[0] / 3;
    int n  = in_sizes[1] / 3;
    int r  = in_sizes[5] / 3;

    int grid = (nx + MTILE - 1) / MTILE;
    rbf_tps_mma_kernel<<<grid, BLOCK>>>(x, y, shift, scale, coeffs, powers,
                                        (float*)d_out, nx, n, r);
}

// round 4
// speedup vs baseline: 1.8189x; 1.1203x over previous
#include <cuda_runtime.h>
#include <cstdint>

#define BLOCK 128
#define MTILE 64
#define MM 16
#define NMAX 8192

// packed preprocessed operands (prologue kernel fills these)
__device__ float4   g_y4[NMAX];                    // (-2yx, -2yy, -2yz, |y|^2)
__device__ uint32_t g_bh[(NMAX / 2) * MM];         // bf16x2(coeff[2p][c], coeff[2p+1][c]) hi
__device__ uint32_t g_bl[(NMAX / 2) * MM];         // residual lo

__device__ __forceinline__ uint32_t pack_bf16x2(float lo, float hi) {
    uint32_t d;
    asm("cvt.rn.bf16x2.f32 %0, %1, %2;" : "=r"(d) : "f"(hi), "f"(lo));
    return d;
}

__device__ __forceinline__ void split2(float f0, float f1, uint32_t& hi, uint32_t& lo) {
    hi = pack_bf16x2(f0, f1);
    float h0 = __uint_as_float(hi << 16);
    float h1 = __uint_as_float(hi & 0xffff0000u);
    lo = pack_bf16x2(f0 - h0, f1 - h1);
}

__device__ __forceinline__ void mma_bf16(float* c, const uint32_t* a, uint32_t b0, uint32_t b1) {
    asm volatile(
        "mma.sync.aligned.m16n8k16.row.col.f32.bf16.bf16.f32 "
        "{%0,%1,%2,%3}, {%4,%5,%6,%7}, {%8,%9}, {%0,%1,%2,%3};"
        : "+f"(c[0]), "+f"(c[1]), "+f"(c[2]), "+f"(c[3])
        : "r"(a[0]), "r"(a[1]), "r"(a[2]), "r"(a[3]), "r"(b0), "r"(b1));
}

// phi = r^2 log r = 0.5*ln2 * s * lg2(s), s = |x-y|^2; y pre-packed as (-2y, |y|^2)
__device__ __forceinline__ float phi_f(float4 xr, float4 v) {
    float t = fmaf(xr.x, v.x, fmaf(xr.y, v.y, fmaf(xr.z, v.z, v.w)));
    float s = xr.w + t;
    s = fmaxf(s, 1e-14f);
    return (0.34657359027997264f * s) * __log2f(s);
}

// ---------------- prologue: pack y and split coeffs ----------------
__global__ void prep_kernel(const float* __restrict__ y,
                            const float* __restrict__ coeffs,
                            int n, int npad) {
    int i = blockIdx.x * blockDim.x + threadIdx.x;
    if (i < npad) {
        float4 v = make_float4(0.f, 0.f, 0.f, 1.f);
        if (i < n) {
            float a = y[3 * i], b = y[3 * i + 1], c = y[3 * i + 2];
            v = make_float4(-2.f * a, -2.f * b, -2.f * c, fmaf(a, a, fmaf(b, b, c * c)));
        }
        g_y4[i] = v;
    }
    int npe = (npad >> 1) * MM;
    if (i < npe) {
        int p = i >> 4, c = i & 15;
        int j0 = 2 * p, j1 = 2 * p + 1;
        float f0 = (j0 < n) ? coeffs[(size_t)j0 * MM + c] : 0.f;
        float f1 = (j1 < n) ? coeffs[(size_t)j1 * MM + c] : 0.f;
        uint32_t hi, lo;
        split2(f0, f1, hi, lo);
        g_bh[i] = hi;
        g_bl[i] = lo;
    }
}

// ---------------- main kernel ----------------
__global__ __launch_bounds__(BLOCK) void rbf_tps_mma_kernel(
    const float* __restrict__ x,
    const float* __restrict__ shift,
    const float* __restrict__ scale,
    const float* __restrict__ coeffs,
    const int*   __restrict__ powers,
    float* __restrict__ out,
    int nx, int n, int npad, int r)
{
    __shared__ float sred[2][32][MM];   // partials from warps 2,3

    const int tid  = threadIdx.x;
    const int lane = tid & 31;
    const int w    = tid >> 5;
    const int t4   = lane & 3;
    const int g    = lane >> 2;
    const int rowhalf = w & 1;      // which 32-row half of the 64-row tile
    const int jhalf   = w >> 1;     // which pair of k-steps in each 64-chunk

    const int rowbase = blockIdx.x * MTILE + rowhalf * 32;

    // x rows for this lane: rowbase + g + 8*i, with |x|^2 in .w
    float4 xr[4];
#pragma unroll
    for (int i = 0; i < 4; ++i) {
        int row = rowbase + g + 8 * i;
        float4 v = make_float4(0.f, 0.f, 0.f, 0.f);
        if (row < nx) {
            v.x = x[3 * row + 0];
            v.y = x[3 * row + 1];
            v.z = x[3 * row + 2];
            v.w = fmaf(v.x, v.x, fmaf(v.y, v.y, v.z * v.z));
        }
        xr[i] = v;
    }

    float acc[2][2][4];
#pragma unroll
    for (int a = 0; a < 2; ++a)
#pragma unroll
        for (int b = 0; b < 2; ++b)
#pragma unroll
            for (int c = 0; c < 4; ++c) acc[a][b][c] = 0.f;

    const int nchunks = npad >> 6;

    for (int t = 0; t < nchunks; ++t) {
#pragma unroll
        for (int kk = 0; kk < 2; ++kk) {
            const int jb = t * 64 + (jhalf * 2 + kk) * 16;
            const int j0 = jb + 2 * t4;

            float4 v0 = g_y4[j0];
            float4 v1 = g_y4[j0 + 1];
            float4 v2 = g_y4[j0 + 8];
            float4 v3 = g_y4[j0 + 9];

            const int p0 = (jb >> 1) + t4;
            uint32_t bh[2][2], bl[2][2];
#pragma unroll
            for (int nt = 0; nt < 2; ++nt) {
                int c = g + 8 * nt;
                bh[nt][0] = g_bh[p0 * MM + c];
                bh[nt][1] = g_bh[(p0 + 4) * MM + c];
                bl[nt][0] = g_bl[p0 * MM + c];
                bl[nt][1] = g_bl[(p0 + 4) * MM + c];
            }

#pragma unroll
            for (int rt = 0; rt < 2; ++rt) {
                float4 xa = xr[2 * rt], xb = xr[2 * rt + 1];
                float p00 = phi_f(xa, v0), p01 = phi_f(xa, v1);
                float p02 = phi_f(xa, v2), p03 = phi_f(xa, v3);
                float p10 = phi_f(xb, v0), p11 = phi_f(xb, v1);
                float p12 = phi_f(xb, v2), p13 = phi_f(xb, v3);

                uint32_t ah[4], al[4];
                split2(p00, p01, ah[0], al[0]);
                split2(p10, p11, ah[1], al[1]);
                split2(p02, p03, ah[2], al[2]);
                split2(p12, p13, ah[3], al[3]);

#pragma unroll
                for (int nt = 0; nt < 2; ++nt) {
                    mma_bf16(acc[rt][nt], ah, bh[nt][0], bh[nt][1]);
                    mma_bf16(acc[rt][nt], al, bh[nt][0], bh[nt][1]);
                    mma_bf16(acc[rt][nt], ah, bl[nt][0], bl[nt][1]);
                }
            }
        }
    }

    // ---- combine j-halves: warps 2,3 hand partials to warps 0,1 ----
    if (w >= 2) {
#pragma unroll
        for (int rt = 0; rt < 2; ++rt)
#pragma unroll
            for (int nt = 0; nt < 2; ++nt)
#pragma unroll
                for (int q = 0; q < 4; ++q)
                    sred[w - 2][lane][rt * 8 + nt * 4 + q] = acc[rt][nt][q];
    }
    __syncthreads();
    if (w >= 2) return;

#pragma unroll
    for (int rt = 0; rt < 2; ++rt)
#pragma unroll
        for (int nt = 0; nt < 2; ++nt)
#pragma unroll
            for (int q = 0; q < 4; ++q)
                acc[rt][nt][q] += sred[w][lane][rt * 8 + nt * 4 + q];

    // ---- epilogue: polynomial part + store ----
    const float sh0 = __ldg(&shift[0]), sh1 = __ldg(&shift[1]), sh2 = __ldg(&shift[2]);
    const float sl0 = __ldg(&scale[0]), sl1 = __ldg(&scale[1]), sl2 = __ldg(&scale[2]);

#pragma unroll
    for (int i = 0; i < 4; ++i) {
        int grow = rowbase + g + 8 * i;
        if (grow >= nx) continue;
        float4 xc = xr[i];
        float xh0 = (xc.x - sh0) / sl0;
        float xh1 = (xc.y - sh1) / sl1;
        float xh2 = (xc.z - sh2) / sl2;
        const int rt = i >> 1, up = i & 1;

#pragma unroll
        for (int nt = 0; nt < 2; ++nt) {
            const int col = 2 * t4 + 8 * nt;
            float o0 = acc[rt][nt][up * 2 + 0];
            float o1 = acc[rt][nt][up * 2 + 1];
            for (int k = 0; k < r; ++k) {
                float p = 1.f;
                int e0 = __ldg(&powers[k * 3 + 0]);
                int e1 = __ldg(&powers[k * 3 + 1]);
                int e2 = __ldg(&powers[k * 3 + 2]);
                for (int q = 0; q < e0; ++q) p *= xh0;
                for (int q = 0; q < e1; ++q) p *= xh1;
                for (int q = 0; q < e2; ++q) p *= xh2;
                float cc0 = __ldg(&coeffs[(size_t)(n + k) * MM + col]);
                float cc1 = __ldg(&coeffs[(size_t)(n + k) * MM + col + 1]);
                o0 = fmaf(p, cc0, o0);
                o1 = fmaf(p, cc1, o1);
            }
            *reinterpret_cast<float2*>(&out[(size_t)grow * MM + col]) = make_float2(o0, o1);
        }
    }
}

extern "C" void kernel_launch(void* const* d_in, const int* in_sizes, int n_in,
                              void* d_out, int out_size) {
    const float* x      = (const float*)d_in[0];
    const float* y      = (const float*)d_in[1];
    const float* shift  = (const float*)d_in[2];
    const float* scale  = (const float*)d_in[3];
    const float* coeffs = (const float*)d_in[4];
    const int*   powers = (const int*)d_in[5];

    int nx = in_sizes[0] / 3;
    int n  = in_sizes[1] / 3;
    int r  = in_sizes[5] / 3;

    int npad = (n + 63) & ~63;
    if (npad > NMAX) npad = NMAX;

    int prep_work = (npad >> 1) * MM;
    if (npad > prep_work) prep_work = npad;
    prep_kernel<<<(prep_work + 255) / 256, 256>>>(y, coeffs, n, npad);

    int grid = (nx + MTILE - 1) / MTILE;
    rbf_tps_mma_kernel<<<grid, BLOCK>>>(x, shift, scale, coeffs, powers,
                                        (float*)d_out, nx, n, npad, r);
}